// round 1
// baseline (speedup 1.0000x reference)
#include <cuda_runtime.h>
#include <math.h>

#define BATCH 32
#define CH    128
#define NPIX  4096
#define HEADS 4
#define DH    32
#define HID   128
#define TPIX  64
#define NTILE (NPIX / TPIX)   // 64
#define SCALE_Q 0.17677669529663687f  // 32^-0.5

// -------- scratch (device globals; no allocation allowed) --------
__device__ float g_s[BATCH * NPIX];                               // inv-norm scale per pixel
__device__ float g_qsoft[(size_t)BATCH * HID * NPIX];             // softmaxed q * scale
__device__ float g_Spart[(size_t)BATCH * NTILE * HEADS * DH * DH];// per-tile context partials
__device__ float g_Zpart[(size_t)BATCH * NTILE * HID];            // per-tile k-softmax denom partials
__device__ float g_M[BATCH * HID * HID];                          // w_out folded with context

// ================= K1: per-pixel RMS norm scale =================
__global__ void k_norm(const float* __restrict__ x) {
    int b = blockIdx.y;
    int i = blockIdx.x * blockDim.x + threadIdx.x;
    const float* xp = x + (size_t)b * CH * NPIX + i;
    float ss = 0.f;
#pragma unroll 8
    for (int c = 0; c < CH; c++) {
        float v = xp[(size_t)c * NPIX];
        ss = fmaf(v, v, ss);
    }
    g_s[b * NPIX + i] = sqrtf((float)CH) / fmaxf(sqrtf(ss), 1e-12f);
}

// ================= K2: fused qkv GEMM + q softmax + partial context =================
// smem layout (floats): sx[128*64] | sw[16*128] | sbuf[128*66] | sg[128] | ssc[64]
#define K2_SMEM_FLOATS (CH*TPIX + 16*HID + HID*66 + CH + TPIX)
#define K2_SMEM_BYTES  (K2_SMEM_FLOATS * 4)

__global__ void __launch_bounds__(256) k_qkv(const float* __restrict__ x,
                                             const float* __restrict__ g,
                                             const float* __restrict__ wqkv) {
    extern __shared__ float sm[];
    float* sx   = sm;                    // [CH][TPIX] scaled x tile, later reused for v
    float* sw   = sx + CH * TPIX;        // [16][HID] weight stage
    float* sbuf = sw + 16 * HID;         // [HID][66] q buffer, then exp(k) buffer
    float* sg   = sbuf + HID * 66;       // [CH]
    float* ssc  = sg + CH;               // [TPIX]

    const int tid  = threadIdx.x;
    const int b    = blockIdx.y;
    const int tile = blockIdx.x;
    const int i0   = tile * TPIX;

    if (tid < CH) sg[tid] = g[tid];
    if (tid >= CH && tid < CH + TPIX) ssc[tid - CH] = g_s[b * NPIX + i0 + (tid - CH)];
    __syncthreads();

    // load x tile with g[c]*sqrt(C)/norm folded in
    const float* xb = x + (size_t)b * CH * NPIX;
    for (int idx = tid; idx < CH * TPIX; idx += 256) {
        int c = idx >> 6, i = idx & 63;
        sx[idx] = xb[(size_t)c * NPIX + i0 + i] * sg[c] * ssc[i];
    }
    __syncthreads();

    const int to = tid >> 4;   // 0..15 -> owns o rows to*8..to*8+7
    const int ti = tid & 15;   // 0..15 -> owns i cols ti*4..ti*4+3
    float acc[8][4];

    for (int chunk = 0; chunk < 3; chunk++) {
#pragma unroll
        for (int r = 0; r < 8; r++)
#pragma unroll
            for (int q = 0; q < 4; q++) acc[r][q] = 0.f;

        const float* wbase = wqkv + chunk * HID * CH;
        for (int c0 = 0; c0 < CH; c0 += 16) {
            // stage sw[cc][o] = wbase[o][c0+cc]
            {
                int o   = tid >> 1;
                int ch8 = (tid & 1) * 8;
                const float* wp = wbase + o * CH + c0 + ch8;
#pragma unroll
                for (int k = 0; k < 8; k++) sw[(ch8 + k) * HID + o] = wp[k];
            }
            __syncthreads();
#pragma unroll
            for (int cc = 0; cc < 16; cc++) {
                int c = c0 + cc;
                const float4 w0 = *(const float4*)(sw + cc * HID + to * 8);
                const float4 w1 = *(const float4*)(sw + cc * HID + to * 8 + 4);
                const float4 xv = *(const float4*)(sx + c * TPIX + ti * 4);
                float wr[8] = {w0.x, w0.y, w0.z, w0.w, w1.x, w1.y, w1.z, w1.w};
                float xr[4] = {xv.x, xv.y, xv.z, xv.w};
#pragma unroll
                for (int r = 0; r < 8; r++)
#pragma unroll
                    for (int q = 0; q < 4; q++)
                        acc[r][q] = fmaf(wr[r], xr[q], acc[r][q]);
            }
            __syncthreads();
        }

        if (chunk == 0) {
            // ---- q: softmax over d per (h,i), scale, write to global ----
#pragma unroll
            for (int r = 0; r < 8; r++)
#pragma unroll
                for (int q = 0; q < 4; q++)
                    sbuf[(to * 8 + r) * 66 + ti * 4 + q] = acc[r][q];
            __syncthreads();
            {
                int h = tid >> 6, i = tid & 63;   // 4*64 = 256 pairs
                float m = -1e30f;
                for (int d = 0; d < DH; d++) m = fmaxf(m, sbuf[(h * DH + d) * 66 + i]);
                float sum = 0.f;
                for (int d = 0; d < DH; d++) {
                    float e = expf(sbuf[(h * DH + d) * 66 + i] - m);
                    sbuf[(h * DH + d) * 66 + i] = e;
                    sum += e;
                }
                float rs = SCALE_Q / sum;
                float* qg = g_qsoft + ((size_t)b * HID + h * DH) * NPIX + i0 + i;
                for (int d = 0; d < DH; d++)
                    qg[(size_t)d * NPIX] = sbuf[(h * DH + d) * 66 + i] * rs;
            }
            __syncthreads();
        } else if (chunk == 1) {
            // ---- k: store exp(k) (no max needed; values bounded) ----
#pragma unroll
            for (int r = 0; r < 8; r++)
#pragma unroll
                for (int q = 0; q < 4; q++)
                    sbuf[(to * 8 + r) * 66 + ti * 4 + q] = expf(acc[r][q]);
            __syncthreads();
        } else {
            // ---- v: reuse sx region (all reads of sx finished after last sync) ----
#pragma unroll
            for (int r = 0; r < 8; r++)
#pragma unroll
                for (int q = 0; q < 4; q++)
                    sx[(to * 8 + r) * TPIX + ti * 4 + q] = acc[r][q];
            __syncthreads();
        }
    }

    // ---- partial context S[h,d,e] = sum_i exp(k[h,d,i]) * v[h,e,i] ----
    {
        int h  = tid >> 6;
        int d  = (tid & 63) >> 1;
        int eb = (tid & 1) * 16;
        float s16[16];
#pragma unroll
        for (int e = 0; e < 16; e++) s16[e] = 0.f;
        const float* ekrow = sbuf + (h * DH + d) * 66;
        const float* vb    = sx + (h * DH + eb) * TPIX;
        for (int i = 0; i < TPIX; i++) {
            float ek = ekrow[i];
#pragma unroll
            for (int e = 0; e < 16; e++)
                s16[e] = fmaf(ek, vb[e * TPIX + i], s16[e]);
        }
        float* sp = g_Spart + (size_t)(b * NTILE + tile) * (HEADS * DH * DH)
                    + h * DH * DH + d * DH + eb;
#pragma unroll
        for (int e = 0; e < 16; e++) sp[e] = s16[e];
    }
    // ---- partial Z[o] = sum_i exp(k[o,i]) ----
    if (tid < HID) {
        float z = 0.f;
        const float* r = sbuf + tid * 66;
        for (int i = 0; i < TPIX; i++) z += r[i];
        g_Zpart[(size_t)(b * NTILE + tile) * HID + tid] = z;
    }
}

// ================= K3: reduce partials, add mem_kv, fold context into w_out =================
__global__ void __launch_bounds__(256) k_ctx(const float* __restrict__ mem_kv,
                                             const float* __restrict__ w_out) {
    __shared__ float sctx[HEADS * DH * DH];  // 16KB
    __shared__ float sZ[HID];
    int b = blockIdx.x, tid = threadIdx.x;

    if (tid < HID) {
        int h = tid >> 5, d = tid & 31;
        float z = 0.f;
        for (int t = 0; t < NTILE; t++)
            z += g_Zpart[(size_t)(b * NTILE + t) * HID + tid];
        const float* mk = mem_kv + (h * DH + d) * 4;
        for (int j = 0; j < 4; j++) z += expf(mk[j]);
        sZ[tid] = z;
    }
    __syncthreads();

    for (int idx = tid; idx < HEADS * DH * DH; idx += 256) {
        int h = idx >> 10, d = (idx >> 5) & 31, e = idx & 31;
        float s = 0.f;
        for (int t = 0; t < NTILE; t++)
            s += g_Spart[(size_t)(b * NTILE + t) * (HEADS * DH * DH) + idx];
        const float* mk = mem_kv + (h * DH + d) * 4;
        const float* mv = mem_kv + (HEADS * DH + h * DH + e) * 4;
        for (int j = 0; j < 4; j++) s = fmaf(expf(mk[j]), mv[j], s);
        sctx[idx] = s / sZ[h * DH + d];
    }
    __syncthreads();

    // M[co][h*32+d] = sum_e w_out[co][h*32+e] * ctx[h][d][e]
    for (int oidx = tid; oidx < HID * HID; oidx += 256) {
        int co = oidx >> 7, hd = oidx & 127;
        int h = hd >> 5, d = hd & 31;
        const float* wrow = w_out + co * HID + h * DH;
        const float* crow = sctx + h * DH * DH + d * DH;
        float m = 0.f;
#pragma unroll
        for (int e = 0; e < DH; e++) m = fmaf(wrow[e], crow[e], m);
        g_M[(size_t)(b * HID + co) * HID + hd] = m;
    }
}

// ================= K4: output GEMM: out = M @ qsoft + b_out =================
#define K4_SMEM_FLOATS (HID*TPIX + 16*HID)
#define K4_SMEM_BYTES  (K4_SMEM_FLOATS * 4)

__global__ void __launch_bounds__(256) k_out(const float* __restrict__ b_out,
                                             float* __restrict__ out) {
    extern __shared__ float sm[];
    float* sx = sm;               // [HID][TPIX] qsoft tile
    float* sw = sx + HID * TPIX;  // [16][HID]
    __shared__ float sb[HID];

    int tid = threadIdx.x, b = blockIdx.y, tile = blockIdx.x;
    int i0 = tile * TPIX;
    if (tid < HID) sb[tid] = b_out[tid];

    const float* qb = g_qsoft + (size_t)b * HID * NPIX;
    for (int idx = tid; idx < HID * TPIX; idx += 256) {
        int p = idx >> 6, i = idx & 63;
        sx[idx] = qb[(size_t)p * NPIX + i0 + i];
    }
    __syncthreads();

    int to = tid >> 4, ti = tid & 15;
    float acc[8][4];
#pragma unroll
    for (int r = 0; r < 8; r++)
#pragma unroll
        for (int q = 0; q < 4; q++) acc[r][q] = 0.f;

    const float* wbase = g_M + (size_t)b * HID * HID;
    for (int c0 = 0; c0 < HID; c0 += 16) {
        {
            int o = tid >> 1;
            int ch8 = (tid & 1) * 8;
            const float* wp = wbase + o * HID + c0 + ch8;
#pragma unroll
            for (int k = 0; k < 8; k++) sw[(ch8 + k) * HID + o] = wp[k];
        }
        __syncthreads();
#pragma unroll
        for (int cc = 0; cc < 16; cc++) {
            int c = c0 + cc;
            const float4 w0 = *(const float4*)(sw + cc * HID + to * 8);
            const float4 w1 = *(const float4*)(sw + cc * HID + to * 8 + 4);
            const float4 xv = *(const float4*)(sx + c * TPIX + ti * 4);
            float wr[8] = {w0.x, w0.y, w0.z, w0.w, w1.x, w1.y, w1.z, w1.w};
            float xr[4] = {xv.x, xv.y, xv.z, xv.w};
#pragma unroll
            for (int r = 0; r < 8; r++)
#pragma unroll
                for (int q = 0; q < 4; q++)
                    acc[r][q] = fmaf(wr[r], xr[q], acc[r][q]);
        }
        __syncthreads();
    }

#pragma unroll
    for (int r = 0; r < 8; r++) {
        int o = to * 8 + r;
        float bias = sb[o];
        float4 v;
        v.x = acc[r][0] + bias;
        v.y = acc[r][1] + bias;
        v.z = acc[r][2] + bias;
        v.w = acc[r][3] + bias;
        *(float4*)(out + ((size_t)b * HID + o) * NPIX + i0 + ti * 4) = v;
    }
}

// ================= launch =================
extern "C" void kernel_launch(void* const* d_in, const int* in_sizes, int n_in,
                              void* d_out, int out_size) {
    const float* x     = (const float*)d_in[0];
    const float* g     = (const float*)d_in[1];
    const float* wqkv  = (const float*)d_in[2];
    const float* memkv = (const float*)d_in[3];
    const float* wout  = (const float*)d_in[4];
    const float* bout  = (const float*)d_in[5];
    float* out = (float*)d_out;

    // idempotent, deterministic, not a stream op (safe under graph capture)
    cudaFuncSetAttribute(k_qkv, cudaFuncAttributeMaxDynamicSharedMemorySize, K2_SMEM_BYTES);

    k_norm<<<dim3(NPIX / 256, BATCH), 256>>>(x);
    k_qkv<<<dim3(NTILE, BATCH), 256, K2_SMEM_BYTES>>>(x, g, wqkv);
    k_ctx<<<BATCH, 256>>>(memkv, wout);
    k_out<<<dim3(NTILE, BATCH), 256, K4_SMEM_BYTES>>>(bout, out);
}

// round 2
// speedup vs baseline: 2.3657x; 2.3657x over previous
#include <cuda_runtime.h>
#include <math.h>
#include <stdint.h>

#define BATCH 32
#define CH    128
#define NPIX  4096
#define HEADS 4
#define DH    32
#define HID   128
#define TPIX  64
#define NTILE (NPIX / TPIX)   // 64
#define SCALE_Q 0.17677669529663687f  // 32^-0.5

#define PX 72   // x/v tile pitch   (banks: 8*c + n -> conflict-free frags)
#define PW 68   // weight pitch     (banks: 4*o + k -> conflict-free frags)
#define PQ 68   // q/ek pitch

// -------- scratch (device globals; no allocation allowed) --------
__device__ float g_qsoft[(size_t)BATCH * HID * NPIX];              // softmaxed q * scale (tf32 bits)
__device__ float g_Spart[(size_t)BATCH * NTILE * HEADS * DH * DH]; // per-tile context partials
__device__ float g_Zpart[(size_t)BATCH * NTILE * HID];             // per-tile k-softmax denom partials
__device__ float g_M[BATCH * HID * HID];                           // w_out folded with context

__device__ __forceinline__ float to_tf32(float x) {
    uint32_t u;
    asm("cvt.rna.tf32.f32 %0, %1;" : "=r"(u) : "f"(x));
    return __uint_as_float(u);
}

__device__ __forceinline__ void mma8(float* c,
                                     uint32_t a0, uint32_t a1, uint32_t a2, uint32_t a3,
                                     uint32_t b0, uint32_t b1) {
    asm volatile(
        "mma.sync.aligned.m16n8k8.row.col.f32.tf32.tf32.f32 "
        "{%0,%1,%2,%3},{%4,%5,%6,%7},{%8,%9},{%0,%1,%2,%3};"
        : "+f"(c[0]), "+f"(c[1]), "+f"(c[2]), "+f"(c[3])
        : "r"(a0), "r"(a1), "r"(a2), "r"(a3), "r"(b0), "r"(b1));
}

// ================= K2: fused norm + qkv GEMM (tf32 mma) + q softmax + partial context =================
#define K2_SMEM_FLOATS (CH*PX + HID*PW + HID*PQ + 128 + 256)
#define K2_SMEM_BYTES  (K2_SMEM_FLOATS * 4)

__global__ void __launch_bounds__(256) k_qkv(const float* __restrict__ x,
                                             const float* __restrict__ g,
                                             const float* __restrict__ wqkv) {
    extern __shared__ float sm[];
    float* sx    = sm;                 // [CH][PX]  x tile (tf32), later v tile
    float* sw    = sx + CH * PX;       // [HID][PW] weight half-K stage
    float* sqk   = sw + HID * PW;      // [HID][PQ] q buffer, then exp(k)
    float* sg    = sqk + HID * PQ;     // [128]
    float* snorm = sg + 128;           // [256]

    const int tid  = threadIdx.x;
    const int b    = blockIdx.y;
    const int tile = blockIdx.x;
    const int i0   = tile * TPIX;
    const int warp = tid >> 5, lane = tid & 31;
    const int ty   = lane >> 2, tx = lane & 3;

    if (tid < 128) sg[tid] = g[tid];

    // load raw x tile (coalesced float4)
    const float* xb = x + (size_t)b * CH * NPIX;
#pragma unroll
    for (int t = 0; t < 8; t++) {
        int e = tid + t * 256;
        int c = e >> 4, i4 = (e & 15) << 2;
        float4 v = *(const float4*)(xb + (size_t)c * NPIX + i0 + i4);
        *(float4*)(sx + c * PX + i4) = v;
    }
    __syncthreads();

    // per-pixel sum of squares (4 channel-groups of 32)
    {
        int pix = tid & 63, grp = tid >> 6;
        float ss = 0.f;
#pragma unroll
        for (int j = 0; j < 32; j++) {
            float v = sx[(grp * 32 + j) * PX + pix];
            ss = fmaf(v, v, ss);
        }
        snorm[grp * 64 + pix] = ss;
    }
    __syncthreads();
    if (tid < 64) {
        float s = snorm[tid] + snorm[64 + tid] + snorm[128 + tid] + snorm[192 + tid];
        snorm[tid] = 11.313708498984760f / fmaxf(sqrtf(s), 1e-12f);  // sqrt(128)/norm
    }
    __syncthreads();
    // scale + convert to tf32 in place
#pragma unroll
    for (int t = 0; t < 32; t++) {
        int e = tid + t * 256;
        int c = e >> 6, i = e & 63;
        sx[c * PX + i] = to_tf32(sx[c * PX + i] * sg[c] * snorm[i]);
    }
    // (sync before first GEMM read happens at kh-loop head)

    float acc[8][4];
    for (int chunk = 0; chunk < 3; chunk++) {
#pragma unroll
        for (int nt = 0; nt < 8; nt++) {
            acc[nt][0] = 0.f; acc[nt][1] = 0.f; acc[nt][2] = 0.f; acc[nt][3] = 0.f;
        }
        for (int kh = 0; kh < 2; kh++) {
            __syncthreads();
            // stage weights [o][k-half] as tf32, pitch PW
#pragma unroll
            for (int t = 0; t < 8; t++) {
                int e = tid + t * 256;
                int o = e >> 4, k4 = (e & 15) << 2;
                float4 wv = *(const float4*)(wqkv + (size_t)(chunk * HID + o) * CH + kh * 64 + k4);
                sw[o * PW + k4]     = to_tf32(wv.x);
                sw[o * PW + k4 + 1] = to_tf32(wv.y);
                sw[o * PW + k4 + 2] = to_tf32(wv.z);
                sw[o * PW + k4 + 3] = to_tf32(wv.w);
            }
            __syncthreads();
#pragma unroll
            for (int ks = 0; ks < 8; ks++) {
                int kk = ks * 8;
                const float* swb = sw + warp * 16 * PW + kk;
                uint32_t a0 = __float_as_uint(swb[ty * PW + tx]);
                uint32_t a1 = __float_as_uint(swb[(ty + 8) * PW + tx]);
                uint32_t a2 = __float_as_uint(swb[ty * PW + tx + 4]);
                uint32_t a3 = __float_as_uint(swb[(ty + 8) * PW + tx + 4]);
                const float* sxb = sx + (kh * 64 + kk) * PX + ty;
#pragma unroll
                for (int nt = 0; nt < 8; nt++) {
                    uint32_t b0 = __float_as_uint(sxb[tx * PX + nt * 8]);
                    uint32_t b1 = __float_as_uint(sxb[(tx + 4) * PX + nt * 8]);
                    mma8(acc[nt], a0, a1, a2, a3, b0, b1);
                }
            }
        }

        if (chunk == 0) {
            // ---- q: store to sqk, softmax over d, scale, write tf32 q to gmem ----
#pragma unroll
            for (int nt = 0; nt < 8; nt++) {
                int r = warp * 16 + ty, c = nt * 8 + 2 * tx;
                sqk[r * PQ + c]           = acc[nt][0];
                sqk[r * PQ + c + 1]       = acc[nt][1];
                sqk[(r + 8) * PQ + c]     = acc[nt][2];
                sqk[(r + 8) * PQ + c + 1] = acc[nt][3];
            }
            __syncthreads();
            {
                int h = tid >> 6, i = tid & 63;
                const float* qrow = sqk + h * DH * PQ + i;
                float m = -1e30f;
#pragma unroll
                for (int d = 0; d < DH; d++) m = fmaxf(m, qrow[d * PQ]);
                float s = 0.f;
#pragma unroll
                for (int d = 0; d < DH; d++) s += __expf(qrow[d * PQ] - m);
                float rs = SCALE_Q / s;
                float* qg = g_qsoft + ((size_t)b * HID + h * DH) * NPIX + i0 + i;
#pragma unroll
                for (int d = 0; d < DH; d++)
                    qg[(size_t)d * NPIX] = to_tf32(__expf(qrow[d * PQ] - m) * rs);
            }
        } else if (chunk == 1) {
            // ---- k: store exp(k) as tf32 (bounded, no max needed) ----
#pragma unroll
            for (int nt = 0; nt < 8; nt++) {
                int r = warp * 16 + ty, c = nt * 8 + 2 * tx;
                sqk[r * PQ + c]           = to_tf32(__expf(acc[nt][0]));
                sqk[r * PQ + c + 1]       = to_tf32(__expf(acc[nt][1]));
                sqk[(r + 8) * PQ + c]     = to_tf32(__expf(acc[nt][2]));
                sqk[(r + 8) * PQ + c + 1] = to_tf32(__expf(acc[nt][3]));
            }
            __syncthreads();
            if (tid < 128) {
                float z = 0.f;
                const float* rr = sqk + tid * PQ;
#pragma unroll
                for (int i = 0; i < 64; i++) z += rr[i];
                g_Zpart[(size_t)(b * NTILE + tile) * HID + tid] = z;
            }
        } else {
            // ---- v: park accums -> overwrite sx with v (tf32), then context mma ----
            __syncthreads();  // all warps done reading sx
#pragma unroll
            for (int nt = 0; nt < 8; nt++) {
                int r = warp * 16 + ty, c = nt * 8 + 2 * tx;
                sx[r * PX + c]           = to_tf32(acc[nt][0]);
                sx[r * PX + c + 1]       = to_tf32(acc[nt][1]);
                sx[(r + 8) * PX + c]     = to_tf32(acc[nt][2]);
                sx[(r + 8) * PX + c + 1] = to_tf32(acc[nt][3]);
            }
            __syncthreads();
            // S[h,d,e] = sum_i ek[h,d,i] * v[h,e,i] via mma (A=ek rows, B=v^T)
            int h = warp >> 1, dbase = (warp & 1) * 16;
            float cacc[4][4];
#pragma unroll
            for (int et = 0; et < 4; et++) {
                cacc[et][0] = 0.f; cacc[et][1] = 0.f; cacc[et][2] = 0.f; cacc[et][3] = 0.f;
            }
#pragma unroll
            for (int ks = 0; ks < 8; ks++) {
                int ii = ks * 8;
                const float* ab = sqk + (h * DH + dbase) * PQ + ii;
                uint32_t a0 = __float_as_uint(ab[ty * PQ + tx]);
                uint32_t a1 = __float_as_uint(ab[(ty + 8) * PQ + tx]);
                uint32_t a2 = __float_as_uint(ab[ty * PQ + tx + 4]);
                uint32_t a3 = __float_as_uint(ab[(ty + 8) * PQ + tx + 4]);
                const float* bb = sx + h * DH * PX + ii;
#pragma unroll
                for (int et = 0; et < 4; et++) {
                    uint32_t b0 = __float_as_uint(bb[(et * 8 + ty) * PX + tx]);
                    uint32_t b1 = __float_as_uint(bb[(et * 8 + ty) * PX + tx + 4]);
                    mma8(cacc[et], a0, a1, a2, a3, b0, b1);
                }
            }
            float* sp = g_Spart + ((size_t)(b * NTILE + tile)) * (HEADS * DH * DH) + h * DH * DH;
#pragma unroll
            for (int et = 0; et < 4; et++) {
                int d = dbase + ty, e = et * 8 + 2 * tx;
                sp[d * DH + e]           = cacc[et][0];
                sp[d * DH + e + 1]       = cacc[et][1];
                sp[(d + 8) * DH + e]     = cacc[et][2];
                sp[(d + 8) * DH + e + 1] = cacc[et][3];
            }
        }
    }
}

// ================= K3: reduce partials, add mem_kv, fold context into w_out =================
__global__ void __launch_bounds__(256) k_ctx(const float* __restrict__ mem_kv,
                                             const float* __restrict__ w_out) {
    __shared__ float sctx[HEADS * DH * DH];
    __shared__ float sZ[HID];
    int b = blockIdx.x, tid = threadIdx.x;

    if (tid < HID) {
        int h = tid >> 5, d = tid & 31;
        float z = 0.f;
        for (int t = 0; t < NTILE; t++)
            z += g_Zpart[(size_t)(b * NTILE + t) * HID + tid];
        const float* mk = mem_kv + (h * DH + d) * 4;
        for (int j = 0; j < 4; j++) z += __expf(mk[j]);
        sZ[tid] = z;
    }
    __syncthreads();

    for (int idx = tid; idx < HEADS * DH * DH; idx += 256) {
        int h = idx >> 10, d = (idx >> 5) & 31, e = idx & 31;
        float s = 0.f;
        for (int t = 0; t < NTILE; t++)
            s += g_Spart[(size_t)(b * NTILE + t) * (HEADS * DH * DH) + idx];
        const float* mk = mem_kv + (h * DH + d) * 4;
        const float* mv = mem_kv + (HEADS * DH + h * DH + e) * 4;
        for (int j = 0; j < 4; j++) s = fmaf(__expf(mk[j]), mv[j], s);
        sctx[idx] = s / sZ[h * DH + d];
    }
    __syncthreads();

    // M[co][h*32+d] = sum_e w_out[co][h*32+e] * ctx[h][d][e]
    for (int oidx = tid; oidx < HID * HID; oidx += 256) {
        int co = oidx >> 7, hd = oidx & 127;
        int h = hd >> 5, d = hd & 31;
        const float* wrow = w_out + co * HID + h * DH;
        const float* crow = sctx + h * DH * DH + d * DH;
        float m = 0.f;
#pragma unroll
        for (int e = 0; e < DH; e++) m = fmaf(wrow[e], crow[e], m);
        g_M[(size_t)(b * HID + co) * HID + hd] = m;
    }
}

// ================= K4: output GEMM (tf32 mma): out = M @ qsoft + b_out =================
#define PWM 132
#define K4_SMEM_FLOATS (CH*PX + HID*PWM)
#define K4_SMEM_BYTES  (K4_SMEM_FLOATS * 4)

__global__ void __launch_bounds__(256) k_out(const float* __restrict__ bout,
                                             float* __restrict__ out) {
    extern __shared__ float sm[];
    float* sx = sm;               // [128][PX] q tile (already tf32 bits)
    float* sw = sx + CH * PX;     // [128][PWM] M (tf32); reused as output stage [128][66]
    __shared__ float sb[HID];

    const int tid  = threadIdx.x;
    const int b    = blockIdx.y;
    const int tile = blockIdx.x;
    const int i0   = tile * TPIX;
    const int warp = tid >> 5, lane = tid & 31;
    const int ty   = lane >> 2, tx = lane & 3;

    if (tid < HID) sb[tid] = bout[tid];

    const float* qb = g_qsoft + (size_t)b * HID * NPIX;
#pragma unroll
    for (int t = 0; t < 8; t++) {
        int e = tid + t * 256;
        int p = e >> 4, i4 = (e & 15) << 2;
        float4 v = *(const float4*)(qb + (size_t)p * NPIX + i0 + i4);
        *(float4*)(sx + p * PX + i4) = v;
    }
    const float* Mb = g_M + (size_t)b * HID * HID;
#pragma unroll
    for (int t = 0; t < 16; t++) {
        int e = tid + t * 256;
        int o = e >> 5, k4 = (e & 31) << 2;
        float4 wv = *(const float4*)(Mb + o * HID + k4);
        sw[o * PWM + k4]     = to_tf32(wv.x);
        sw[o * PWM + k4 + 1] = to_tf32(wv.y);
        sw[o * PWM + k4 + 2] = to_tf32(wv.z);
        sw[o * PWM + k4 + 3] = to_tf32(wv.w);
    }
    __syncthreads();

    float acc[8][4];
#pragma unroll
    for (int nt = 0; nt < 8; nt++) {
        acc[nt][0] = 0.f; acc[nt][1] = 0.f; acc[nt][2] = 0.f; acc[nt][3] = 0.f;
    }
#pragma unroll 4
    for (int ks = 0; ks < 16; ks++) {
        int kk = ks * 8;
        const float* swb = sw + warp * 16 * PWM + kk;
        uint32_t a0 = __float_as_uint(swb[ty * PWM + tx]);
        uint32_t a1 = __float_as_uint(swb[(ty + 8) * PWM + tx]);
        uint32_t a2 = __float_as_uint(swb[ty * PWM + tx + 4]);
        uint32_t a3 = __float_as_uint(swb[(ty + 8) * PWM + tx + 4]);
        const float* sxb = sx + kk * PX + ty;
#pragma unroll
        for (int nt = 0; nt < 8; nt++) {
            uint32_t b0 = __float_as_uint(sxb[tx * PX + nt * 8]);
            uint32_t b1 = __float_as_uint(sxb[(tx + 4) * PX + nt * 8]);
            mma8(acc[nt], a0, a1, a2, a3, b0, b1);
        }
    }
    __syncthreads();
    // stage output (+bias) into sw region, then coalesced copy out
#pragma unroll
    for (int nt = 0; nt < 8; nt++) {
        int r = warp * 16 + ty, c = nt * 8 + 2 * tx;
        sw[r * 66 + c]           = acc[nt][0] + sb[r];
        sw[r * 66 + c + 1]       = acc[nt][1] + sb[r];
        sw[(r + 8) * 66 + c]     = acc[nt][2] + sb[r + 8];
        sw[(r + 8) * 66 + c + 1] = acc[nt][3] + sb[r + 8];
    }
    __syncthreads();
    float* ob = out + (size_t)b * HID * NPIX + i0;
#pragma unroll
    for (int t = 0; t < 32; t++) {
        int e = tid + t * 256;
        int o = e >> 6, i = e & 63;
        ob[(size_t)o * NPIX + i] = sw[o * 66 + i];
    }
}

// ================= launch =================
extern "C" void kernel_launch(void* const* d_in, const int* in_sizes, int n_in,
                              void* d_out, int out_size) {
    const float* x     = (const float*)d_in[0];
    const float* g     = (const float*)d_in[1];
    const float* wqkv  = (const float*)d_in[2];
    const float* memkv = (const float*)d_in[3];
    const float* wout  = (const float*)d_in[4];
    const float* bout  = (const float*)d_in[5];
    float* out = (float*)d_out;

    cudaFuncSetAttribute(k_qkv, cudaFuncAttributeMaxDynamicSharedMemorySize, K2_SMEM_BYTES);
    cudaFuncSetAttribute(k_out, cudaFuncAttributeMaxDynamicSharedMemorySize, K4_SMEM_BYTES);

    k_qkv<<<dim3(NTILE, BATCH), 256, K2_SMEM_BYTES>>>(x, g, wqkv);
    k_ctx<<<BATCH, 256>>>(memkv, wout);
    k_out<<<dim3(NTILE, BATCH), 256, K4_SMEM_BYTES>>>(bout, out);
}